// round 14
// baseline (speedup 1.0000x reference)
#include <cuda_runtime.h>
#include <cuda_bf16.h>

// LengthRegulator, fused single kernel (gather form, chain-deduped loads).
// out[b,t,:] = x[b, searchsorted(cumsum(dur[b]), t, 'right'), :], zeroed where
// t >= total[b]. mel_mask appended to d_out as float 0/1.

#define BB 32
#define NN 1024
#define DD 384
#define ML 4096
#define D4 (DD / 4)            // 96 float4 per row
#define NROWS (BB * ML)        // 131072 output rows
#define TPB 256
#define ROWS_PB 32             // rows per block (8 warps x 4 rows)
#define BPB (ML / ROWS_PB)     // 128 blocks per batch

__global__ void __launch_bounds__(TPB) fused_kernel(
    const float4* __restrict__ x4,
    float4* __restrict__ out4,
    const int* __restrict__ dur,
    float* __restrict__ mask_out,
    int write_mask
) {
    const int b    = blockIdx.x >> 7;       // / BPB
    const int seg  = blockIdx.x & (BPB - 1);
    const int tid  = threadIdx.x;
    const int lane = tid & 31;
    const int w    = tid >> 5;

    __shared__ int s_cum[NN];
    __shared__ int wsum[8];

    // ---- block scan of 1024 durations (4 per thread via int4) ----
    int4 dv = ((const int4*)(dur + b * NN))[tid];
    const int a0 = dv.x;
    const int a1 = a0 + dv.y;
    const int a2 = a1 + dv.z;
    const int a3 = a2 + dv.w;
    const int tsum = a3;

    int inc = tsum;
    #pragma unroll
    for (int o = 1; o < 32; o <<= 1) {
        int n = __shfl_up_sync(0xFFFFFFFFu, inc, o);
        if (lane >= o) inc += n;
    }
    if (lane == 31) wsum[w] = inc;
    __syncthreads();

    int woff = 0;
    #pragma unroll
    for (int i = 0; i < 8; i++) {
        int wv = wsum[i];
        woff += (i < w) ? wv : 0;
    }
    const int base = woff + (inc - tsum);   // exclusive prefix for this thread

    s_cum[4 * tid + 0] = base + a0;
    s_cum[4 * tid + 1] = base + a1;
    s_cum[4 * tid + 2] = base + a2;
    s_cum[4 * tid + 3] = base + a3;
    __syncthreads();

    const int total = s_cum[NN - 1];

    // ---- searches: warp w owns rows tloc0..tloc0+3; lane (lane&3) searches ----
    const int tloc0 = seg * ROWS_PB + w * 4;
    const int tt = tloc0 + (lane & 3);

    int pos = 0;
    #pragma unroll
    for (int step = NN >> 1; step >= 1; step >>= 1) {
        int np = pos + step;
        if (s_cum[np - 1] <= tt) pos = np;
    }
    const int idx = pos < (NN - 1) ? pos : (NN - 1);
    const int meta_mine = (tt >= total) ? -1 : (b * NN + idx) * D4;

    int m[4];
    #pragma unroll
    for (int r = 0; r < 4; r++) m[r] = __shfl_sync(0xFFFFFFFFu, meta_mine, r);

    // ---- mask: threads 0..31 write this block's 32 mask values ----
    if (write_mask && tid < ROWS_PB) {
        const int tm = seg * ROWS_PB + tid;
        mask_out[b * ML + tm] = (float)(tm >= total);
    }

    // ---- chain-deduped copy: keep one source row live (3 float4), reload
    //      only when the source changes. All branches warp-uniform. ----
    const float4 z = make_float4(0.f, 0.f, 0.f, 0.f);
    float4 v0 = z, v1 = z, v2 = z;
    int cur = -2;                           // -2 = nothing loaded yet

    float4* d = out4 + ((size_t)b * ML + tloc0) * D4;
    #pragma unroll
    for (int r = 0; r < 4; r++) {
        if (m[r] != cur) {
            cur = m[r];
            if (cur >= 0) {
                v0 = x4[cur + lane];
                v1 = x4[cur + lane + 32];
                v2 = x4[cur + lane + 64];
            } else {
                v0 = z; v1 = z; v2 = z;
            }
        }
        __stcs(d + lane,      v0);
        __stcs(d + lane + 32, v1);
        __stcs(d + lane + 64, v2);
        d += D4;
    }
}

extern "C" void kernel_launch(void* const* d_in, const int* in_sizes, int n_in,
                              void* d_out, int out_size) {
    const float* x   = (const float*)d_in[0];
    const int*   dur = (const int*)d_in[1];
    float*       out = (float*)d_out;

    const long long out_elems  = (long long)NROWS * DD;
    const long long mask_elems = (long long)NROWS;
    int write_mask = ((long long)out_size >= out_elems + mask_elems) ? 1 : 0;
    float* mask_out = write_mask ? (out + out_elems) : nullptr;

    fused_kernel<<<BB * BPB, TPB>>>((const float4*)x, (float4*)out, dur,
                                    mask_out, write_mask);
}